// round 11
// baseline (speedup 1.0000x reference)
#include <cuda_runtime.h>
#include <cstdint>

// FurthestPointsSample: x [B,3,N] f32 -> out [B,3,1024] f32. B=16, N=65536.
//
// Primary (cluster-16): one 16-CTA cluster per PAIR of batches; each CTA holds
// 4096 pts of batch A and 4096 of batch B (registers, packed f32x2) + SMEM
// mirrors. The two FPS chains are software-pipelined: A's DSMEM exchange
// flight is hidden under B's compute phase and vice versa. All mbarrier
// parities are STATELESS (computed from `it`) -> uniform across lanes.
// Fallback (cluster-8): the proven R4 kernel.

#define N_PTS   65536
#define NPOINTS 1024
#define THREADS 1024

__device__ __forceinline__ unsigned ctarank() {
    unsigned r; asm("mov.u32 %0, %%cluster_ctarank;" : "=r"(r)); return r;
}
__device__ __forceinline__ void cluster_sync_all() {
    asm volatile("barrier.cluster.arrive.aligned;\n\t"
                 "barrier.cluster.wait.aligned;" ::: "memory");
}
__device__ __forceinline__ unsigned mapa_sh(unsigned addr, unsigned rank) {
    unsigned r;
    asm("mapa.shared::cluster.u32 %0, %1, %2;" : "=r"(r) : "r"(addr), "r"(rank));
    return r;
}
__device__ __forceinline__ unsigned long long addx2(unsigned long long a, unsigned long long b) {
    unsigned long long r; asm("add.rn.f32x2 %0, %1, %2;" : "=l"(r) : "l"(a), "l"(b)); return r;
}
__device__ __forceinline__ unsigned long long mulx2(unsigned long long a, unsigned long long b) {
    unsigned long long r; asm("mul.rn.f32x2 %0, %1, %2;" : "=l"(r) : "l"(a), "l"(b)); return r;
}
__device__ __forceinline__ unsigned long long packf2(float lo, float hi) {
    unsigned long long r; asm("mov.b64 %0, {%1, %2};" : "=l"(r) : "f"(lo), "f"(hi)); return r;
}
__device__ __forceinline__ void unpackf2(unsigned long long v, float& lo, float& hi) {
    asm("mov.b64 {%0, %1}, %2;" : "=f"(lo), "=f"(hi) : "l"(v));
}
__device__ __forceinline__ unsigned long long pack_fu(float z, unsigned hi) {
    unsigned long long r; asm("mov.b64 %0, {%1, %2};" : "=l"(r) : "f"(z), "r"(hi)); return r;
}
__device__ __forceinline__ void st_async_u64(unsigned addr, unsigned long long v, unsigned mbar) {
    asm volatile("st.async.shared::cluster.mbarrier::complete_tx::bytes.b64 [%0], %1, [%2];"
                 :: "r"(addr), "l"(v), "r"(mbar) : "memory");
}
__device__ __forceinline__ void mbar_init(unsigned addr, unsigned cnt) {
    asm volatile("mbarrier.init.shared.b64 [%0], %1;" :: "r"(addr), "r"(cnt) : "memory");
}
__device__ __forceinline__ void mbar_expect_tx(unsigned addr, unsigned tx) {
    asm volatile("mbarrier.arrive.expect_tx.shared.b64 _, [%0], %1;"
                 :: "r"(addr), "r"(tx) : "memory");
}
__device__ __forceinline__ void mbar_wait(unsigned addr, unsigned phase) {
    asm volatile(
        "{\n\t.reg .pred P;\n\t"
        "LAB_%=:\n\t"
        "mbarrier.try_wait.parity.acquire.cta.shared::cta.b64 P, [%0], %1, 0x989680;\n\t"
        "@!P bra LAB_%=;\n\t}"
        :: "r"(addr), "r"(phase) : "memory");
}

extern __shared__ float smem_dyn[];

// ==================== PAIRED KERNEL (cluster 16) ====================
#define CL16    16
#define PPC16   (N_PTS / CL16)      // 4096 per batch per CTA
#define PPT16   (PPC16 / THREADS)   // 4
#define NPR16   (PPT16 / 2)         // 2
#define EXP16   (CL16 * 16)         // 256 bytes per barrier per round

__global__ void __launch_bounds__(THREADS, 1)
fps_paired_kernel(const float* __restrict__ x, float* __restrict__ out)
{
    __shared__ unsigned long long warp_keyA[32], warp_keyB[32];
    __shared__ __align__(16) float slotmem[2][2][CL16][4];   // [par][batch][rank]
    __shared__ float4 bcastA_s, bcastB_s;
    __shared__ __align__(8) unsigned long long mbar[2][2];   // [par][batch]

    const unsigned r    = ctarank();
    const unsigned pb   = blockIdx.x / CL16;
    const unsigned tid  = threadIdx.x;
    const unsigned lane = tid & 31u;
    const unsigned wid  = tid >> 5;

    const float* __restrict__ xbA = x + (size_t)(2 * pb) * 3u * N_PTS;
    const float* __restrict__ ybA = xbA + N_PTS;
    const float* __restrict__ zbA = xbA + 2 * N_PTS;
    const float* __restrict__ xbB = xbA + 3 * N_PTS;
    const float* __restrict__ ybB = xbB + N_PTS;
    const float* __restrict__ zbB = xbB + 2 * N_PTS;
    float* __restrict__ obA = out + (size_t)(2 * pb) * 3u * NPOINTS;
    float* __restrict__ obB = obA + 3 * NPOINTS;

    float* xsA = smem_dyn;     float* ysA = xsA + PPC16;  float* zsA = ysA + PPC16;
    float* xsB = zsA + PPC16;  float* ysB = xsB + PPC16;  float* zsB = ysB + PPC16;

    const unsigned slot_base = (unsigned)__cvta_generic_to_shared(&slotmem[0][0][0][0]);
    const unsigned bar_base  = (unsigned)__cvta_generic_to_shared(&mbar[0][0]);

    if (tid < 4) mbar_init(bar_base + tid * 8u, 1);

    unsigned long long pxA[NPR16], pyA[NPR16], pzA[NPR16];
    unsigned long long pxB[NPR16], pyB[NPR16], pzB[NPR16];
    float dA[PPT16], dB[PPT16];
    const unsigned gbase = r * PPC16 + tid;
#pragma unroll
    for (int p = 0; p < NPR16; p++) {
        unsigned l0 = tid + (unsigned)(2 * p) * THREADS, l1 = l0 + THREADS;
        unsigned g0 = r * PPC16 + l0, g1 = r * PPC16 + l1;
        float ax0 = xbA[g0], ax1 = xbA[g1], ay0 = ybA[g0], ay1 = ybA[g1];
        float az0 = zbA[g0], az1 = zbA[g1];
        pxA[p] = packf2(ax0, ax1); pyA[p] = packf2(ay0, ay1); pzA[p] = packf2(az0, az1);
        xsA[l0] = ax0; xsA[l1] = ax1; ysA[l0] = ay0; ysA[l1] = ay1; zsA[l0] = az0; zsA[l1] = az1;
        float bx0 = xbB[g0], bx1 = xbB[g1], by0 = ybB[g0], by1 = ybB[g1];
        float bz0 = zbB[g0], bz1 = zbB[g1];
        pxB[p] = packf2(bx0, bx1); pyB[p] = packf2(by0, by1); pzB[p] = packf2(bz0, bz1);
        xsB[l0] = bx0; xsB[l1] = bx1; ysB[l0] = by0; ysB[l1] = by1; zsB[l0] = bz0; zsB[l1] = bz1;
        dA[2 * p] = 1e10f; dA[2 * p + 1] = 1e10f;
        dB[2 * p] = 1e10f; dB[2 * p + 1] = 1e10f;
    }

    float fxA = __ldg(xbA), fyA = __ldg(ybA), fzA = __ldg(zbA);
    float fxB = __ldg(xbB), fyB = __ldg(ybB), fzB = __ldg(zbB);
    if (tid == 0) {
        bcastB_s = make_float4(fxB, fyB, fzB, 0.0f);
        if (r == 0) {
            obA[0] = fxA; obA[NPOINTS] = fyA; obA[2 * NPOINTS] = fzA;
            obB[0] = fxB; obB[NPOINTS] = fyB; obB[2 * NPOINTS] = fzB;
        }
    }
    __syncthreads();
    cluster_sync_all();

    unsigned long long nlxA = packf2(-fxA, -fxA), nlyA = packf2(-fyA, -fyA), nlzA = packf2(-fzA, -fzA);
    unsigned long long nlxB = packf2(-fxB, -fxB), nlyB = packf2(-fyB, -fyB), nlzB = packf2(-fzB, -fzB);

    for (int it = 1; it < NPOINTS; it++) {
        const int par = it & 1;
        const unsigned barA = bar_base + (unsigned)(par * 2 + 0) * 8u;
        const unsigned barB = bar_base + (unsigned)(par * 2 + 1) * 8u;
        // Stateless parities (uniform across all lanes).
        const unsigned pA = (unsigned)(((it - 2 + (it & 1)) >> 1) & 1);

        if (tid == 0) { mbar_expect_tx(barA, EXP16); mbar_expect_tx(barB, EXP16); }

        // ======== A compute (winner it-1) ========
        float bestd = -1.0f; int bestj = 0;
#pragma unroll
        for (int p = 0; p < NPR16; p++) {
            unsigned long long dx = addx2(pxA[p], nlxA);
            unsigned long long dy = addx2(pyA[p], nlyA);
            unsigned long long dz = addx2(pzA[p], nlzA);
            unsigned long long s  = addx2(addx2(mulx2(dx, dx), mulx2(dy, dy)), mulx2(dz, dz));
            float s0, s1; unpackf2(s, s0, s1);
            float nd0 = fminf(dA[2 * p], s0);     dA[2 * p]     = nd0;
            float nd1 = fminf(dA[2 * p + 1], s1); dA[2 * p + 1] = nd1;
            bool c0 = nd0 > bestd; bestd = c0 ? nd0 : bestd; bestj = c0 ? 2 * p : bestj;
            bool c1 = nd1 > bestd; bestd = c1 ? nd1 : bestd; bestj = c1 ? 2 * p + 1 : bestj;
        }
        {
            unsigned bits = __float_as_uint(bestd);
            unsigned wmax = __reduce_max_sync(0xffffffffu, bits);
            unsigned g    = gbase + (unsigned)bestj * THREADS;
            unsigned cand = (bits == wmax) ? ~g : 0u;
            unsigned wi   = __reduce_max_sync(0xffffffffu, cand);
            if (lane == 0) warp_keyA[wid] = ((unsigned long long)wmax << 32) | wi;
        }
        __syncthreads();   // S1

        if (wid == 0) {
            unsigned long long k = warp_keyA[lane];
            unsigned hb = (unsigned)(k >> 32);
            unsigned hm = __reduce_max_sync(0xffffffffu, hb);
            unsigned lo = (hb == hm) ? (unsigned)k : 0u;
            unsigned lm = __reduce_max_sync(0xffffffffu, lo);
            if (lane < CL16) {
                unsigned local = (~lm) & (PPC16 - 1);
                float wx = xsA[local], wy = ysA[local], wz = zsA[local];
                unsigned lslot = slot_base + (unsigned)((par * 2 + 0) * CL16 + (int)r) * 16u;
                st_async_u64(mapa_sh(lslot, lane),      packf2(wx, wy), mapa_sh(barA, lane));
                st_async_u64(mapa_sh(lslot, lane) + 8,  pack_fu(wz, hm), mapa_sh(barA, lane));
            }
        } else if (wid == 1 && it >= 2) {
            // B recv: winner j = it-1
            const int j  = it - 1;
            const int pp = j & 1;
            const unsigned pB = (unsigned)(((j - 2 + (j & 1)) >> 1) & 1);
            mbar_wait(bar_base + (unsigned)(pp * 2 + 1) * 8u, pB);
            float4 s = *(const float4*)&slotmem[pp][1][lane & (CL16 - 1)][0];
            unsigned db = __float_as_uint(s.w);
            unsigned m  = __reduce_max_sync(0xffffffffu, db);
            unsigned bal = __ballot_sync(0xffffffffu, (lane < CL16) && (db == m));
            if (lane == (unsigned)(__ffs(bal) - 1)) {
                bcastB_s = s;
                if (r == 0) {
                    obB[j] = s.x; obB[NPOINTS + j] = s.y; obB[2 * NPOINTS + j] = s.z;
                }
            }
        }
        __syncthreads();   // S2

        {
            float4 wb = bcastB_s;
            nlxB = packf2(-wb.x, -wb.x); nlyB = packf2(-wb.y, -wb.y); nlzB = packf2(-wb.z, -wb.z);
        }

        // ======== B compute (winner it-1) ========
        bestd = -1.0f; bestj = 0;
#pragma unroll
        for (int p = 0; p < NPR16; p++) {
            unsigned long long dx = addx2(pxB[p], nlxB);
            unsigned long long dy = addx2(pyB[p], nlyB);
            unsigned long long dz = addx2(pzB[p], nlzB);
            unsigned long long s  = addx2(addx2(mulx2(dx, dx), mulx2(dy, dy)), mulx2(dz, dz));
            float s0, s1; unpackf2(s, s0, s1);
            float nd0 = fminf(dB[2 * p], s0);     dB[2 * p]     = nd0;
            float nd1 = fminf(dB[2 * p + 1], s1); dB[2 * p + 1] = nd1;
            bool c0 = nd0 > bestd; bestd = c0 ? nd0 : bestd; bestj = c0 ? 2 * p : bestj;
            bool c1 = nd1 > bestd; bestd = c1 ? nd1 : bestd; bestj = c1 ? 2 * p + 1 : bestj;
        }
        {
            unsigned bits = __float_as_uint(bestd);
            unsigned wmax = __reduce_max_sync(0xffffffffu, bits);
            unsigned g    = gbase + (unsigned)bestj * THREADS;
            unsigned cand = (bits == wmax) ? ~g : 0u;
            unsigned wi   = __reduce_max_sync(0xffffffffu, cand);
            if (lane == 0) warp_keyB[wid] = ((unsigned long long)wmax << 32) | wi;
        }
        __syncthreads();   // S3

        if (wid == 1) {
            unsigned long long k = warp_keyB[lane];
            unsigned hb = (unsigned)(k >> 32);
            unsigned hm = __reduce_max_sync(0xffffffffu, hb);
            unsigned lo = (hb == hm) ? (unsigned)k : 0u;
            unsigned lm = __reduce_max_sync(0xffffffffu, lo);
            if (lane < CL16) {
                unsigned local = (~lm) & (PPC16 - 1);
                float wx = xsB[local], wy = ysB[local], wz = zsB[local];
                unsigned lslot = slot_base + (unsigned)((par * 2 + 1) * CL16 + (int)r) * 16u;
                st_async_u64(mapa_sh(lslot, lane),     packf2(wx, wy), mapa_sh(barB, lane));
                st_async_u64(mapa_sh(lslot, lane) + 8, pack_fu(wz, hm), mapa_sh(barB, lane));
            }
        } else if (wid == 0) {
            // A recv: winner it (flight hidden under B phase)
            mbar_wait(barA, pA);
            float4 s = *(const float4*)&slotmem[par][0][lane & (CL16 - 1)][0];
            unsigned db = __float_as_uint(s.w);
            unsigned m  = __reduce_max_sync(0xffffffffu, db);
            unsigned bal = __ballot_sync(0xffffffffu, (lane < CL16) && (db == m));
            if (lane == (unsigned)(__ffs(bal) - 1)) {
                bcastA_s = s;
                if (r == 0) {
                    obA[it] = s.x; obA[NPOINTS + it] = s.y; obA[2 * NPOINTS + it] = s.z;
                }
            }
        }
        __syncthreads();   // S4

        {
            float4 wa = bcastA_s;
            nlxA = packf2(-wa.x, -wa.x); nlyA = packf2(-wa.y, -wa.y); nlzA = packf2(-wa.z, -wa.z);
        }
    }

    // Epilogue: consume B winner j=1023 (parity ((1023-2+1)>>1)&1 = 1).
    if (wid == 1) {
        mbar_wait(bar_base + (unsigned)(1 * 2 + 1) * 8u, 1u);
        float4 s = *(const float4*)&slotmem[1][1][lane & (CL16 - 1)][0];
        unsigned db = __float_as_uint(s.w);
        unsigned m  = __reduce_max_sync(0xffffffffu, db);
        unsigned bal = __ballot_sync(0xffffffffu, (lane < CL16) && (db == m));
        if (r == 0 && lane == (unsigned)(__ffs(bal) - 1)) {
            obB[NPOINTS - 1] = s.x; obB[2 * NPOINTS - 1] = s.y; obB[3 * NPOINTS - 1] = s.z;
        }
    }
}

// ==================== FALLBACK KERNEL (cluster 8, R4) ====================
#define CLUSTER 8
#define PPC     (N_PTS / CLUSTER)   // 8192
#define PPT     (PPC / THREADS)     // 8
#define NPAIR   (PPT / 2)           // 4
#define MSG_TX  16

__global__ void __launch_bounds__(THREADS, 1) __cluster_dims__(CLUSTER, 1, 1)
fps_cluster_kernel(const float* __restrict__ x, float* __restrict__ out)
{
    __shared__ unsigned long long warp_key[32];
    __shared__ __align__(16) float slotmem[2][CLUSTER][4];
    __shared__ float4 bcast[2];
    __shared__ __align__(8) unsigned long long mbar[2];

    const unsigned r    = ctarank();
    const unsigned b    = blockIdx.x / CLUSTER;
    const unsigned tid  = threadIdx.x;
    const unsigned lane = tid & 31u;
    const unsigned wid  = tid >> 5;

    const float* __restrict__ xb = x + (size_t)b * 3u * N_PTS;
    const float* __restrict__ yb = xb + N_PTS;
    const float* __restrict__ zb = xb + 2 * N_PTS;
    float* __restrict__ ob = out + (size_t)b * 3u * NPOINTS;

    float* xs = smem_dyn;
    float* ys = xs + PPC;
    float* zs = ys + PPC;

    const unsigned slot_base = (unsigned)__cvta_generic_to_shared(&slotmem[0][0][0]);
    const unsigned bar_base  = (unsigned)__cvta_generic_to_shared(&mbar[0]);

    if (tid == 0) { mbar_init(bar_base, 1); mbar_init(bar_base + 8, 1); }

    unsigned long long px2[NPAIR], py2[NPAIR], pz2[NPAIR];
    float dist[PPT];
    const unsigned gbase = r * PPC + tid;
#pragma unroll
    for (int p = 0; p < NPAIR; p++) {
        unsigned g0 = gbase + (unsigned)(2 * p) * THREADS;
        unsigned g1 = g0 + THREADS;
        float x0 = xb[g0], x1 = xb[g1];
        float y0 = yb[g0], y1 = yb[g1];
        float z0 = zb[g0], z1 = zb[g1];
        px2[p] = packf2(x0, x1); py2[p] = packf2(y0, y1); pz2[p] = packf2(z0, z1);
        unsigned l0 = tid + (unsigned)(2 * p) * THREADS, l1 = l0 + THREADS;
        xs[l0] = x0; xs[l1] = x1; ys[l0] = y0; ys[l1] = y1; zs[l0] = z0; zs[l1] = z1;
        dist[2 * p] = 1e10f; dist[2 * p + 1] = 1e10f;
    }
    __syncthreads();
    cluster_sync_all();

    float fx = __ldg(xb + 0), fy = __ldg(yb + 0), fz = __ldg(zb + 0);
    if (r == 0 && tid == 0) { ob[0] = fx; ob[NPOINTS] = fy; ob[2 * NPOINTS] = fz; }
    unsigned long long nlx2 = packf2(-fx, -fx);
    unsigned long long nly2 = packf2(-fy, -fy);
    unsigned long long nlz2 = packf2(-fz, -fz);

    unsigned ph0 = 0, ph1 = 0;

    for (int it = 1; it < NPOINTS; it++) {
        const int par = it & 1;
        const unsigned barp = bar_base + (unsigned)par * 8u;
        if (tid == 0) mbar_expect_tx(barp, CLUSTER * MSG_TX);

        float bestd = -1.0f; int bestj = 0;
#pragma unroll
        for (int p = 0; p < NPAIR; p++) {
            unsigned long long dx = addx2(px2[p], nlx2);
            unsigned long long dy = addx2(py2[p], nly2);
            unsigned long long dz = addx2(pz2[p], nlz2);
            unsigned long long s  = addx2(addx2(mulx2(dx, dx), mulx2(dy, dy)), mulx2(dz, dz));
            float s0, s1; unpackf2(s, s0, s1);
            float nd0 = fminf(dist[2 * p], s0);     dist[2 * p]     = nd0;
            float nd1 = fminf(dist[2 * p + 1], s1); dist[2 * p + 1] = nd1;
            bool c0 = nd0 > bestd; bestd = c0 ? nd0 : bestd; bestj = c0 ? 2 * p : bestj;
            bool c1 = nd1 > bestd; bestd = c1 ? nd1 : bestd; bestj = c1 ? 2 * p + 1 : bestj;
        }

        unsigned bits = __float_as_uint(bestd);
        unsigned wmax = __reduce_max_sync(0xffffffffu, bits);
        unsigned g    = gbase + (unsigned)bestj * THREADS;
        unsigned cand = (bits == wmax) ? ~g : 0u;
        unsigned wi   = __reduce_max_sync(0xffffffffu, cand);
        if (lane == 0)
            warp_key[wid] = ((unsigned long long)wmax << 32) | wi;
        __syncthreads();

        if (wid == 0) {
            unsigned long long k = warp_key[lane];
            unsigned hb = (unsigned)(k >> 32);
            unsigned hm = __reduce_max_sync(0xffffffffu, hb);
            unsigned lo = (hb == hm) ? (unsigned)k : 0u;
            unsigned lm = __reduce_max_sync(0xffffffffu, lo);

            if (lane < CLUSTER) {
                unsigned local = (~lm) & (PPC - 1);
                float wx = xs[local], wy = ys[local], wz = zs[local];
                unsigned lslot = slot_base + (unsigned)(par * CLUSTER + (int)r) * 16u;
                unsigned rslot = mapa_sh(lslot, lane);
                unsigned rbar  = mapa_sh(barp, lane);
                st_async_u64(rslot,     packf2(wx, wy), rbar);
                st_async_u64(rslot + 8, pack_fu(wz, hm), rbar);
            }

            mbar_wait(barp, par ? ph1 : ph0);

            float4 s = *(const float4*)&slotmem[par][lane & (CLUSTER - 1)][0];
            unsigned db = __float_as_uint(s.w);
            unsigned m  = __reduce_max_sync(0xffffffffu, db);
            unsigned bal = __ballot_sync(0xffffffffu, (lane < CLUSTER) && (db == m));
            if (lane == (unsigned)(__ffs(bal) - 1)) {
                bcast[par] = s;
                if (r == 0) {
                    ob[it] = s.x; ob[NPOINTS + it] = s.y; ob[2 * NPOINTS + it] = s.z;
                }
            }
        }
        __syncthreads();

        float4 w = bcast[par];
        nlx2 = packf2(-w.x, -w.x);
        nly2 = packf2(-w.y, -w.y);
        nlz2 = packf2(-w.z, -w.z);
        if (par) ph1 ^= 1; else ph0 ^= 1;
    }
}

// ==================== LAUNCH ====================
extern "C" void kernel_launch(void* const* d_in, const int* in_sizes, int n_in,
                              void* d_out, int out_size)
{
    const float* x = (const float*)d_in[0];
    float* out = (float*)d_out;
    int B = in_sizes[0] / (3 * N_PTS);   // 16
    size_t dyn = 3 * (size_t)PPC * sizeof(float);   // 96 KB (both kernels)

    cudaFuncSetAttribute(fps_paired_kernel,
                         cudaFuncAttributeNonPortableClusterSizeAllowed, 1);
    cudaFuncSetAttribute(fps_paired_kernel,
                         cudaFuncAttributeMaxDynamicSharedMemorySize, (int)dyn);
    cudaFuncSetAttribute(fps_cluster_kernel,
                         cudaFuncAttributeMaxDynamicSharedMemorySize, (int)dyn);

    bool paired_ok = false;
    if ((B & 1) == 0) {
        cudaLaunchConfig_t qcfg = {};
        qcfg.gridDim  = dim3((unsigned)(B / 2) * CL16, 1, 1);
        qcfg.blockDim = dim3(THREADS, 1, 1);
        qcfg.dynamicSmemBytes = dyn;
        int maxc = 0;
        cudaError_t qe = cudaOccupancyMaxPotentialClusterSize(&maxc, fps_paired_kernel, &qcfg);
        paired_ok = (qe == cudaSuccess && maxc >= CL16);
        if (qe != cudaSuccess) (void)cudaGetLastError();
    }

    if (paired_ok) {
        cudaLaunchConfig_t cfg = {};
        cfg.gridDim  = dim3((unsigned)(B / 2) * CL16, 1, 1);
        cfg.blockDim = dim3(THREADS, 1, 1);
        cfg.dynamicSmemBytes = dyn;
        cudaLaunchAttribute attrs[1];
        attrs[0].id = cudaLaunchAttributeClusterDimension;
        attrs[0].val.clusterDim.x = CL16;
        attrs[0].val.clusterDim.y = 1;
        attrs[0].val.clusterDim.z = 1;
        cfg.attrs = attrs;
        cfg.numAttrs = 1;
        cudaError_t le = cudaLaunchKernelEx(&cfg, fps_paired_kernel, x, out);
        if (le == cudaSuccess) return;
        (void)cudaGetLastError();   // clear; fall through to proven kernel
    }

    dim3 grid(B * CLUSTER), block(THREADS);
    fps_cluster_kernel<<<grid, block, dyn>>>(x, out);
}

// round 13
// speedup vs baseline: 1.2878x; 1.2878x over previous
#include <cuda_runtime.h>
#include <cstdint>

// FurthestPointsSample: x [B,3,N] f32 -> out [B,3,1024] f32. B=16, N=65536.
// 8-CTA cluster per batch; points register-resident (8/thread, packed f32x2)
// + SMEM mirror. Per round: f32x2 dist update + inline select argmax, REDUX
// reductions, 16-byte st.async all-to-all {x,y}{z,distbits} on ONE mbarrier
// per parity, warp0-only wait + slot reduce + smem broadcast. Remote mapa
// addresses hoisted out of the loop. Tie-break = slot position (contiguous
// rank index ranges). Bit-exact vs the JAX reference (rel_err 0.0).

#define N_PTS   65536
#define CLUSTER 8
#define PPC     (N_PTS / CLUSTER)   // 8192
#define THREADS 1024
#define PPT     (PPC / THREADS)     // 8
#define NPAIR   (PPT / 2)           // 4
#define NPOINTS 1024
#define MSG_TX  16                  // bytes per source CTA: 8 (x,y) + 8 (z,distbits)

__device__ __forceinline__ unsigned ctarank() {
    unsigned r; asm("mov.u32 %0, %%cluster_ctarank;" : "=r"(r)); return r;
}
__device__ __forceinline__ void cluster_sync_all() {
    asm volatile("barrier.cluster.arrive.aligned;\n\t"
                 "barrier.cluster.wait.aligned;" ::: "memory");
}
__device__ __forceinline__ unsigned mapa_sh(unsigned addr, unsigned rank) {
    unsigned r;
    asm("mapa.shared::cluster.u32 %0, %1, %2;" : "=r"(r) : "r"(addr), "r"(rank));
    return r;
}
__device__ __forceinline__ unsigned long long addx2(unsigned long long a, unsigned long long b) {
    unsigned long long r; asm("add.rn.f32x2 %0, %1, %2;" : "=l"(r) : "l"(a), "l"(b)); return r;
}
__device__ __forceinline__ unsigned long long mulx2(unsigned long long a, unsigned long long b) {
    unsigned long long r; asm("mul.rn.f32x2 %0, %1, %2;" : "=l"(r) : "l"(a), "l"(b)); return r;
}
__device__ __forceinline__ unsigned long long packf2(float lo, float hi) {
    unsigned long long r; asm("mov.b64 %0, {%1, %2};" : "=l"(r) : "f"(lo), "f"(hi)); return r;
}
__device__ __forceinline__ void unpackf2(unsigned long long v, float& lo, float& hi) {
    asm("mov.b64 {%0, %1}, %2;" : "=f"(lo), "=f"(hi) : "l"(v));
}
__device__ __forceinline__ unsigned long long pack_fu(float z, unsigned hi) {
    unsigned long long r; asm("mov.b64 %0, {%1, %2};" : "=l"(r) : "f"(z), "r"(hi)); return r;
}
__device__ __forceinline__ void st_async_u64(unsigned addr, unsigned long long v, unsigned mbar) {
    asm volatile("st.async.shared::cluster.mbarrier::complete_tx::bytes.b64 [%0], %1, [%2];"
                 :: "r"(addr), "l"(v), "r"(mbar) : "memory");
}
__device__ __forceinline__ void mbar_init(unsigned addr, unsigned cnt) {
    asm volatile("mbarrier.init.shared.b64 [%0], %1;" :: "r"(addr), "r"(cnt) : "memory");
}
__device__ __forceinline__ void mbar_expect_tx(unsigned addr, unsigned tx) {
    asm volatile("mbarrier.arrive.expect_tx.shared.b64 _, [%0], %1;"
                 :: "r"(addr), "r"(tx) : "memory");
}
__device__ __forceinline__ void mbar_wait(unsigned addr, unsigned phase) {
    asm volatile(
        "{\n\t.reg .pred P;\n\t"
        "LAB_%=:\n\t"
        "mbarrier.try_wait.parity.acquire.cta.shared::cta.b64 P, [%0], %1, 0x989680;\n\t"
        "@!P bra LAB_%=;\n\t}"
        :: "r"(addr), "r"(phase) : "memory");
}

extern __shared__ float smem_dyn[];   // xs[8192] ys[8192] zs[8192] = 96 KB

__global__ void __launch_bounds__(THREADS, 1) __cluster_dims__(CLUSTER, 1, 1)
fps_cluster_kernel(const float* __restrict__ x, float* __restrict__ out)
{
    __shared__ unsigned long long warp_key[32];
    // 16-byte slots: [x f32][y f32][z f32][distbits u32]
    __shared__ __align__(16) float slotmem[2][CLUSTER][4];
    __shared__ float4 bcast[2];
    __shared__ __align__(8) unsigned long long mbar[2];

    const unsigned r    = ctarank();
    const unsigned b    = blockIdx.x / CLUSTER;
    const unsigned tid  = threadIdx.x;
    const unsigned lane = tid & 31u;
    const unsigned wid  = tid >> 5;

    const float* __restrict__ xb = x + (size_t)b * 3u * N_PTS;
    const float* __restrict__ yb = xb + N_PTS;
    const float* __restrict__ zb = xb + 2 * N_PTS;
    float* __restrict__ ob = out + (size_t)b * 3u * NPOINTS;

    float* xs = smem_dyn;
    float* ys = xs + PPC;
    float* zs = ys + PPC;

    const unsigned slot_base = (unsigned)__cvta_generic_to_shared(&slotmem[0][0][0]);
    const unsigned bar_base  = (unsigned)__cvta_generic_to_shared(&mbar[0]);

    if (tid == 0) { mbar_init(bar_base, 1); mbar_init(bar_base + 8, 1); }

    // Hoisted remote addresses (lane t < 8 targets rank t; my slot index = r).
    unsigned rs0 = 0, rs1 = 0, rb0 = 0, rb1 = 0;
    if (lane < CLUSTER) {
        rs0 = mapa_sh(slot_base + (0 * CLUSTER + r) * 16u, lane);
        rs1 = mapa_sh(slot_base + (1 * CLUSTER + r) * 16u, lane);
        rb0 = mapa_sh(bar_base,      lane);
        rb1 = mapa_sh(bar_base + 8u, lane);
    }

    // Load points into registers (packed pairs) + SMEM mirror.
    unsigned long long px2[NPAIR], py2[NPAIR], pz2[NPAIR];
    float dist[PPT];
    const unsigned gbase = r * PPC + tid;
#pragma unroll
    for (int p = 0; p < NPAIR; p++) {
        unsigned g0 = gbase + (unsigned)(2 * p) * THREADS;
        unsigned g1 = g0 + THREADS;
        float x0 = xb[g0], x1 = xb[g1];
        float y0 = yb[g0], y1 = yb[g1];
        float z0 = zb[g0], z1 = zb[g1];
        px2[p] = packf2(x0, x1); py2[p] = packf2(y0, y1); pz2[p] = packf2(z0, z1);
        unsigned l0 = tid + (unsigned)(2 * p) * THREADS, l1 = l0 + THREADS;
        xs[l0] = x0; xs[l1] = x1; ys[l0] = y0; ys[l1] = y1; zs[l0] = z0; zs[l1] = z1;
        dist[2 * p] = 1e10f; dist[2 * p + 1] = 1e10f;
    }
    __syncthreads();
    cluster_sync_all();   // peers' mbarriers + mirrors ready before any st.async

    // First selected point: index 0 (reference convention).
    float fx = __ldg(xb + 0), fy = __ldg(yb + 0), fz = __ldg(zb + 0);
    if (r == 0 && tid == 0) { ob[0] = fx; ob[NPOINTS] = fy; ob[2 * NPOINTS] = fz; }
    unsigned long long nlx2 = packf2(-fx, -fx);
    unsigned long long nly2 = packf2(-fy, -fy);
    unsigned long long nlz2 = packf2(-fz, -fz);

    unsigned ph0 = 0, ph1 = 0;

    for (int it = 1; it < NPOINTS; it++) {
        const int par = it & 1;
        const unsigned barp = bar_base + (unsigned)par * 8u;

        // Arm this round's barrier early (off the critical tail).
        if (tid == 0) mbar_expect_tx(barp, CLUSTER * MSG_TX);

        // ---- dist update + thread-local argmax (bit-exact, first occurrence) ----
        float bestd = -1.0f; int bestj = 0;
#pragma unroll
        for (int p = 0; p < NPAIR; p++) {
            unsigned long long dx = addx2(px2[p], nlx2);
            unsigned long long dy = addx2(py2[p], nly2);
            unsigned long long dz = addx2(pz2[p], nlz2);
            unsigned long long s  = addx2(addx2(mulx2(dx, dx), mulx2(dy, dy)), mulx2(dz, dz));
            float s0, s1; unpackf2(s, s0, s1);
            float nd0 = fminf(dist[2 * p], s0);     dist[2 * p]     = nd0;
            float nd1 = fminf(dist[2 * p + 1], s1); dist[2 * p + 1] = nd1;
            bool c0 = nd0 > bestd; bestd = c0 ? nd0 : bestd; bestj = c0 ? 2 * p : bestj;
            bool c1 = nd1 > bestd; bestd = c1 ? nd1 : bestd; bestj = c1 ? 2 * p + 1 : bestj;
        }

        // ---- warp reduction: max dist bits, then min global index ----
        unsigned bits = __float_as_uint(bestd);
        unsigned wmax = __reduce_max_sync(0xffffffffu, bits);
        unsigned g    = gbase + (unsigned)bestj * THREADS;
        unsigned cand = (bits == wmax) ? ~g : 0u;
        unsigned wi   = __reduce_max_sync(0xffffffffu, cand);
        if (lane == 0)
            warp_key[wid] = ((unsigned long long)wmax << 32) | wi;
        __syncthreads();

        if (wid == 0) {
            // ---- block reduction over 32 warp keys ----
            unsigned long long k = warp_key[lane];
            unsigned hb = (unsigned)(k >> 32);
            unsigned hm = __reduce_max_sync(0xffffffffu, hb);
            unsigned lo = (hb == hm) ? (unsigned)k : 0u;
            unsigned lm = __reduce_max_sync(0xffffffffu, lo);

            // ---- push {x,y,z,distbits} (16 B) to every CTA: lane t -> rank t ----
            if (lane < CLUSTER) {
                unsigned local = (~lm) & (PPC - 1);     // block winner, CTA-local
                float wx = xs[local], wy = ys[local], wz = zs[local];
                unsigned rslot = par ? rs1 : rs0;
                unsigned rbar  = par ? rb1 : rb0;
                st_async_u64(rslot,     packf2(wx, wy), rbar);
                st_async_u64(rslot + 8, pack_fu(wz, hm), rbar);
            }

            // ---- warp0 waits for all 8 messages, reduces the slots ----
            mbar_wait(barp, par ? ph1 : ph0);

            float4 s = *(const float4*)&slotmem[par][lane & (CLUSTER - 1)][0];
            unsigned db = __float_as_uint(s.w);
            unsigned m  = __reduce_max_sync(0xffffffffu, db);
            // Cross-CTA tie-break: rank ranges contiguous ascending, so
            // min global index == min rank == min slot == min lane here.
            unsigned bal = __ballot_sync(0xffffffffu, (lane < CLUSTER) && (db == m));
            if (lane == (unsigned)(__ffs(bal) - 1)) {
                bcast[par] = s;
                if (r == 0) {
                    ob[it] = s.x; ob[NPOINTS + it] = s.y; ob[2 * NPOINTS + it] = s.z;
                }
            }
        }
        __syncthreads();

        float4 w = bcast[par];
        nlx2 = packf2(-w.x, -w.x);
        nly2 = packf2(-w.y, -w.y);
        nlz2 = packf2(-w.z, -w.z);
        if (par) ph1 ^= 1; else ph0 ^= 1;
    }
}

extern "C" void kernel_launch(void* const* d_in, const int* in_sizes, int n_in,
                              void* d_out, int out_size)
{
    const float* x = (const float*)d_in[0];
    float* out = (float*)d_out;
    int B = in_sizes[0] / (3 * N_PTS);   // 16
    size_t dyn = 3 * PPC * sizeof(float);   // 96 KB
    cudaFuncSetAttribute(fps_cluster_kernel,
                         cudaFuncAttributeMaxDynamicSharedMemorySize, (int)dyn);
    dim3 grid(B * CLUSTER), block(THREADS);
    fps_cluster_kernel<<<grid, block, dyn>>>(x, out);
}

// round 14
// speedup vs baseline: 1.2896x; 1.0015x over previous
#include <cuda_runtime.h>
#include <cstdint>

// FurthestPointsSample: x [B,3,N] f32 -> out [B,3,1024] f32. B=16, N=65536.
// 8-CTA cluster per batch; points register-resident (8/thread, packed f32x2)
// + SMEM mirror. Per round: f32x2 dist update, REDUX reductions, 16-byte
// st.async all-to-all {x,y,z,distbits} (tie-break = slot position, since rank
// ranges are contiguous), warp0-only mbar wait + slot reduce + smem broadcast.

#define N_PTS   65536
#define CLUSTER 8
#define PPC     (N_PTS / CLUSTER)   // 8192
#define THREADS 1024
#define PPT     (PPC / THREADS)     // 8
#define NPAIR   (PPT / 2)           // 4
#define NPOINTS 1024
#define MSG_TX  16                  // bytes per source CTA: 8 (x,y) + 8 (z,distbits)

__device__ __forceinline__ unsigned ctarank() {
    unsigned r; asm("mov.u32 %0, %%cluster_ctarank;" : "=r"(r)); return r;
}
__device__ __forceinline__ void cluster_sync_all() {
    asm volatile("barrier.cluster.arrive.aligned;\n\t"
                 "barrier.cluster.wait.aligned;" ::: "memory");
}
__device__ __forceinline__ unsigned mapa_sh(unsigned addr, unsigned rank) {
    unsigned r;
    asm("mapa.shared::cluster.u32 %0, %1, %2;" : "=r"(r) : "r"(addr), "r"(rank));
    return r;
}
__device__ __forceinline__ unsigned long long addx2(unsigned long long a, unsigned long long b) {
    unsigned long long r; asm("add.rn.f32x2 %0, %1, %2;" : "=l"(r) : "l"(a), "l"(b)); return r;
}
__device__ __forceinline__ unsigned long long mulx2(unsigned long long a, unsigned long long b) {
    unsigned long long r; asm("mul.rn.f32x2 %0, %1, %2;" : "=l"(r) : "l"(a), "l"(b)); return r;
}
__device__ __forceinline__ unsigned long long packf2(float lo, float hi) {
    unsigned long long r; asm("mov.b64 %0, {%1, %2};" : "=l"(r) : "f"(lo), "f"(hi)); return r;
}
__device__ __forceinline__ void unpackf2(unsigned long long v, float& lo, float& hi) {
    asm("mov.b64 {%0, %1}, %2;" : "=f"(lo), "=f"(hi) : "l"(v));
}
__device__ __forceinline__ unsigned long long pack_fu(float z, unsigned hi) {
    unsigned long long r; asm("mov.b64 %0, {%1, %2};" : "=l"(r) : "f"(z), "r"(hi)); return r;
}
__device__ __forceinline__ void st_async_u64(unsigned addr, unsigned long long v, unsigned mbar) {
    asm volatile("st.async.shared::cluster.mbarrier::complete_tx::bytes.b64 [%0], %1, [%2];"
                 :: "r"(addr), "l"(v), "r"(mbar) : "memory");
}
__device__ __forceinline__ void mbar_init(unsigned addr, unsigned cnt) {
    asm volatile("mbarrier.init.shared.b64 [%0], %1;" :: "r"(addr), "r"(cnt) : "memory");
}
__device__ __forceinline__ void mbar_expect_tx(unsigned addr, unsigned tx) {
    asm volatile("mbarrier.arrive.expect_tx.shared.b64 _, [%0], %1;"
                 :: "r"(addr), "r"(tx) : "memory");
}
__device__ __forceinline__ void mbar_wait(unsigned addr, unsigned phase) {
    asm volatile(
        "{\n\t.reg .pred P;\n\t"
        "LAB_%=:\n\t"
        "mbarrier.try_wait.parity.acquire.cta.shared::cta.b64 P, [%0], %1, 0x989680;\n\t"
        "@!P bra LAB_%=;\n\t}"
        :: "r"(addr), "r"(phase) : "memory");
}

extern __shared__ float smem_dyn[];   // xs[8192] ys[8192] zs[8192] = 96 KB

__global__ void __launch_bounds__(THREADS, 1) __cluster_dims__(CLUSTER, 1, 1)
fps_cluster_kernel(const float* __restrict__ x, float* __restrict__ out)
{
    __shared__ unsigned long long warp_key[32];
    // 16-byte slots: [x f32][y f32][z f32][distbits u32]
    __shared__ __align__(16) float slotmem[2][CLUSTER][4];
    __shared__ float4 bcast[2];
    __shared__ __align__(8) unsigned long long mbar[2];

    const unsigned r    = ctarank();
    const unsigned b    = blockIdx.x / CLUSTER;
    const unsigned tid  = threadIdx.x;
    const unsigned lane = tid & 31u;
    const unsigned wid  = tid >> 5;

    const float* __restrict__ xb = x + (size_t)b * 3u * N_PTS;
    const float* __restrict__ yb = xb + N_PTS;
    const float* __restrict__ zb = xb + 2 * N_PTS;
    float* __restrict__ ob = out + (size_t)b * 3u * NPOINTS;

    float* xs = smem_dyn;
    float* ys = xs + PPC;
    float* zs = ys + PPC;

    const unsigned slot_base = (unsigned)__cvta_generic_to_shared(&slotmem[0][0][0]);
    const unsigned bar_base  = (unsigned)__cvta_generic_to_shared(&mbar[0]);

    if (tid == 0) { mbar_init(bar_base, 1); mbar_init(bar_base + 8, 1); }

    // Load points into registers (packed pairs) + SMEM mirror.
    unsigned long long px2[NPAIR], py2[NPAIR], pz2[NPAIR];
    float dist[PPT];
    const unsigned gbase = r * PPC + tid;
#pragma unroll
    for (int p = 0; p < NPAIR; p++) {
        unsigned g0 = gbase + (unsigned)(2 * p) * THREADS;
        unsigned g1 = g0 + THREADS;
        float x0 = xb[g0], x1 = xb[g1];
        float y0 = yb[g0], y1 = yb[g1];
        float z0 = zb[g0], z1 = zb[g1];
        px2[p] = packf2(x0, x1); py2[p] = packf2(y0, y1); pz2[p] = packf2(z0, z1);
        unsigned l0 = tid + (unsigned)(2 * p) * THREADS, l1 = l0 + THREADS;
        xs[l0] = x0; xs[l1] = x1; ys[l0] = y0; ys[l1] = y1; zs[l0] = z0; zs[l1] = z1;
        dist[2 * p] = 1e10f; dist[2 * p + 1] = 1e10f;
    }
    __syncthreads();
    cluster_sync_all();   // peers' mbarriers initialized before any st.async

    // First selected point: index 0 (reference convention).
    float fx = __ldg(xb + 0), fy = __ldg(yb + 0), fz = __ldg(zb + 0);
    if (r == 0 && tid == 0) { ob[0] = fx; ob[NPOINTS] = fy; ob[2 * NPOINTS] = fz; }
    unsigned long long nlx2 = packf2(-fx, -fx);
    unsigned long long nly2 = packf2(-fy, -fy);
    unsigned long long nlz2 = packf2(-fz, -fz);

    unsigned ph0 = 0, ph1 = 0;

    for (int it = 1; it < NPOINTS; it++) {
        const int par = it & 1;
        const unsigned barp = bar_base + (unsigned)par * 8u;

        // Arm this round's barrier early (off the critical tail; tx may go
        // pending-negative if remote stores land first — that's legal).
        if (tid == 0) mbar_expect_tx(barp, CLUSTER * MSG_TX);

        // ---- dist update + thread-local argmax (bit-exact, first occurrence) ----
        float bestd = -1.0f; int bestj = 0;
#pragma unroll
        for (int p = 0; p < NPAIR; p++) {
            unsigned long long dx = addx2(px2[p], nlx2);
            unsigned long long dy = addx2(py2[p], nly2);
            unsigned long long dz = addx2(pz2[p], nlz2);
            unsigned long long s  = addx2(addx2(mulx2(dx, dx), mulx2(dy, dy)), mulx2(dz, dz));
            float s0, s1; unpackf2(s, s0, s1);
            float nd0 = fminf(dist[2 * p], s0);     dist[2 * p]     = nd0;
            float nd1 = fminf(dist[2 * p + 1], s1); dist[2 * p + 1] = nd1;
            bool c0 = nd0 > bestd; bestd = c0 ? nd0 : bestd; bestj = c0 ? 2 * p : bestj;
            bool c1 = nd1 > bestd; bestd = c1 ? nd1 : bestd; bestj = c1 ? 2 * p + 1 : bestj;
        }

        // ---- warp reduction: max dist bits, then min global index ----
        unsigned bits = __float_as_uint(bestd);
        unsigned wmax = __reduce_max_sync(0xffffffffu, bits);
        unsigned g    = gbase + (unsigned)bestj * THREADS;
        unsigned cand = (bits == wmax) ? ~g : 0u;
        unsigned wi   = __reduce_max_sync(0xffffffffu, cand);
        if (lane == 0)
            warp_key[wid] = ((unsigned long long)wmax << 32) | wi;
        __syncthreads();

        if (wid == 0) {
            // ---- block reduction over 32 warp keys ----
            unsigned long long k = warp_key[lane];
            unsigned hb = (unsigned)(k >> 32);
            unsigned hm = __reduce_max_sync(0xffffffffu, hb);
            unsigned lo = (hb == hm) ? (unsigned)k : 0u;
            unsigned lm = __reduce_max_sync(0xffffffffu, lo);

            // ---- push {x,y,z,distbits} (16 B) to every CTA: lane t -> rank t ----
            if (lane < CLUSTER) {
                unsigned local = (~lm) & (PPC - 1);     // block winner, CTA-local
                float wx = xs[local], wy = ys[local], wz = zs[local];
                unsigned lslot = slot_base + (unsigned)(par * CLUSTER + (int)r) * 16u;
                unsigned rslot = mapa_sh(lslot, lane);
                unsigned rbar  = mapa_sh(barp, lane);
                st_async_u64(rslot,     packf2(wx, wy), rbar);
                st_async_u64(rslot + 8, pack_fu(wz, hm), rbar);
            }

            // ---- warp0 waits for all 8 messages, reduces the slots ----
            mbar_wait(barp, par ? ph1 : ph0);

            float4 s = *(const float4*)&slotmem[par][lane & (CLUSTER - 1)][0];
            unsigned db = __float_as_uint(s.w);
            unsigned m  = __reduce_max_sync(0xffffffffu, db);
            // Cross-CTA tie-break: rank ranges are contiguous ascending, so
            // min global index == min rank == min slot == min lane here.
            unsigned bal = __ballot_sync(0xffffffffu, (lane < CLUSTER) && (db == m));
            if (lane == (unsigned)(__ffs(bal) - 1)) {
                bcast[par] = s;
                if (r == 0) {
                    ob[it] = s.x; ob[NPOINTS + it] = s.y; ob[2 * NPOINTS + it] = s.z;
                }
            }
        }
        __syncthreads();

        float4 w = bcast[par];
        nlx2 = packf2(-w.x, -w.x);
        nly2 = packf2(-w.y, -w.y);
        nlz2 = packf2(-w.z, -w.z);
        if (par) ph1 ^= 1; else ph0 ^= 1;
    }
}

extern "C" void kernel_launch(void* const* d_in, const int* in_sizes, int n_in,
                              void* d_out, int out_size)
{
    const float* x = (const float*)d_in[0];
    float* out = (float*)d_out;
    int B = in_sizes[0] / (3 * N_PTS);   // 16
    size_t dyn = 3 * PPC * sizeof(float);   // 96 KB
    cudaFuncSetAttribute(fps_cluster_kernel,
                         cudaFuncAttributeMaxDynamicSharedMemorySize, (int)dyn);
    dim3 grid(B * CLUSTER), block(THREADS);
    fps_cluster_kernel<<<grid, block, dyn>>>(x, out);
}